// round 15
// baseline (speedup 1.0000x reference)
#include <cuda_runtime.h>
#include <cuda_bf16.h>
#include <cstdint>

// NLTKHierarchicalSoftmax: B=4096, NHID=512, BR=32, DEPTH=3
// Round 15: single kernel = R6 self-filtering (no sort launch) + R14
// W-stationary smem for L0/L1 + R4 register path for L2.
//   bids [0,128):   level 2 — 8 buckets/CTA self-filtered to smem lists,
//                   warp-per-bucket, R4 register-prefetch W
//   bids [128,192): level 0 — node-0 W in smem (f32x2 pairs), 64 samples/CTA
//   bids [192,256): level 1 — CTA per (node, parity), filtered list,
//                   node W in smem
// Last CTA computes the 3-factor product (g_done counter, reset each launch).

#define FULL 0xffffffffu
#define NHID 512
#define BR 32
#define BTOT 4096
#define WNODE (NHID*BR)
#define NCTA 256
#define CAP1 192                       // L1 half-node list capacity
#define CAP2 64                        // L2 bucket list capacity
#define WPAIRS 8192                    // 256 h-pairs x 32 cols
// dynamic smem: wps (64KB) + xs_tile 8 warps x 8 x 128 floats (32KB)
#define DSMEM_BYTES (WPAIRS * 8 + 8 * 8 * 128 * 4)

__device__ float g_p[3 * BTOT];
__device__ int g_done;                 // zero-init; reset by last CTA

typedef unsigned long long u64t;

__device__ __forceinline__ u64t ffma2(u64t a, u64t b, u64t c)
{
    u64t d;
    asm("fma.rn.f32x2 %0, %1, %2, %3;" : "=l"(d) : "l"(a), "l"(b), "l"(c));
    return d;
}
__device__ __forceinline__ u64t packf2(float lo, float hi)
{
    u64t d;
    asm("mov.b64 %0, {%1, %2};" : "=l"(d) : "f"(lo), "f"(hi));
    return d;
}
__device__ __forceinline__ float2 unpackf2(u64t v)
{
    float2 r;
    asm("mov.b64 {%0, %1}, %2;" : "=f"(r.x), "=f"(r.y) : "l"(v));
    return r;
}

// ---------------- shared softmax/emit -----------------------------------------
template<int TS>
__device__ __forceinline__ void softmax_emit(
    u64t* acc2, unsigned msk, const int* bs, const int* step,
    int lane, float* __restrict__ pout)
{
    #pragma unroll
    for (int s = 0; s < TS; s++) {
        if (msk & (1u << s)) {
            float2 h = unpackf2(acc2[s]);
            float acc = h.x + h.y;
            float m = acc;
            #pragma unroll
            for (int o = 16; o > 0; o >>= 1)
                m = fmaxf(m, __shfl_xor_sync(FULL, m, o));
            float e = __expf(acc - m);
            float sum = e;
            #pragma unroll
            for (int o = 16; o > 0; o >>= 1)
                sum += __shfl_xor_sync(FULL, sum, o);
            float est = __shfl_sync(FULL, e, step[s]);
            if (lane == 0) pout[bs[s]] = est / sum;
        }
    }
    __syncwarp();
}

// ---------------- R4 register-prefetch run (level 2) --------------------------
template<int TS>
__device__ __forceinline__ void process_run_reg(
    const float* __restrict__ x, const float* __restrict__ Wn,
    const int* bs, unsigned msk, const int* step,
    int lane, float (*xsm)[128], float* __restrict__ pout)
{
    u64t acc2[TS];
    #pragma unroll
    for (int s = 0; s < TS; s++) acc2[s] = 0ull;

    float wr[2][16];
    #pragma unroll
    for (int k = 0; k < 16; k++)
        wr[0][k] = __ldg(Wn + k * BR + lane);

    #pragma unroll 1
    for (int sc = 0; sc < 4; sc++) {
        __syncwarp();
        #pragma unroll
        for (int s = 0; s < TS; s++) {
            float4 xv = *(const float4*)(x + (size_t)bs[s] * NHID
                                         + sc * 128 + lane * 4);
            *(float4*)&xsm[s][lane * 4] = xv;
        }
        __syncwarp();

        #pragma unroll
        for (int sub = 0; sub < 8; sub++) {
            const int curb = sub & 1;
            const int subg = sc * 8 + sub;
            if (subg + 1 < 32) {
                int h0 = (subg + 1) * 16;
                #pragma unroll
                for (int k = 0; k < 16; k++)
                    wr[curb ^ 1][k] = __ldg(Wn + (h0 + k) * BR + lane);
            }
            u64t wp[8];
            #pragma unroll
            for (int k = 0; k < 8; k++)
                wp[k] = packf2(wr[curb][2 * k], wr[curb][2 * k + 1]);

            #pragma unroll
            for (int q = 0; q < 4; q++) {
                #pragma unroll
                for (int s = 0; s < TS; s++) {
                    ulonglong2 xq =
                        *(const ulonglong2*)&xsm[s][sub * 16 + q * 4];
                    acc2[s] = ffma2(xq.x, wp[2 * q], acc2[s]);
                    acc2[s] = ffma2(xq.y, wp[2 * q + 1], acc2[s]);
                }
            }
        }
    }
    softmax_emit<TS>(acc2, msk, bs, step, lane, pout);
}

// ---------------- W-stationary smem run (levels 0/1) --------------------------
// wps[(pair)*32 + lane] = {W[2p][lane], W[2p+1][lane]} as f32x2
__device__ __forceinline__ void process_run_smem(
    const float* __restrict__ x, const u64t* __restrict__ wps,
    const int* bs, unsigned msk, const int* step,
    int lane, float (*xsm)[128], float* __restrict__ pout)
{
    u64t acc2[8];
    #pragma unroll
    for (int s = 0; s < 8; s++) acc2[s] = 0ull;

    #pragma unroll 1
    for (int sc = 0; sc < 4; sc++) {
        __syncwarp();
        #pragma unroll
        for (int s = 0; s < 8; s++) {
            float4 xv = *(const float4*)(x + (size_t)bs[s] * NHID
                                         + sc * 128 + lane * 4);
            *(float4*)&xsm[s][lane * 4] = xv;
        }
        __syncwarp();

        #pragma unroll
        for (int sub = 0; sub < 8; sub++) {
            u64t wp[8];
            #pragma unroll
            for (int k = 0; k < 8; k++)
                wp[k] = wps[(sc * 64 + sub * 8 + k) * 32 + lane];  // LDS.64

            #pragma unroll
            for (int q = 0; q < 4; q++) {
                #pragma unroll
                for (int s = 0; s < 8; s++) {
                    ulonglong2 xq =
                        *(const ulonglong2*)&xsm[s][sub * 16 + q * 4];
                    acc2[s] = ffma2(xq.x, wp[2 * q], acc2[s]);
                    acc2[s] = ffma2(xq.y, wp[2 * q + 1], acc2[s]);
                }
            }
        }
    }
    softmax_emit<8>(acc2, msk, bs, step, lane, pout);
}

// ---------------- fused kernel ------------------------------------------------
__global__ void __launch_bounds__(256, 2) k_all(
    const float* __restrict__ x, const int* __restrict__ labels,
    const float* __restrict__ W, float* __restrict__ out, int B)
{
    extern __shared__ __align__(16) u64t dyn[];
    u64t* wps = dyn;                                               // 64KB
    float (*xs_all)[8][128] = reinterpret_cast<float (*)[8][128]>(dyn + WPAIRS);

    __shared__ int s_cnt[8];
    __shared__ int s_list[8][CAP2];
    __shared__ int s_l1list[CAP1];
    __shared__ int s_l1cnt;
    __shared__ int s_last;

    const int tid = threadIdx.x;
    const int lane = tid & 31;
    const int wid = tid >> 5;
    const int c = blockIdx.x;
    float (*xsm)[128] = xs_all[wid];

    if (c < 128) {
        // ------------- level 2: self-filter 8 buckets, R4 register path -------
        if (tid < 8) s_cnt[tid] = 0;
        __syncthreads();
        for (int i = tid; i < B; i += 256) {
            int key = __ldg(&labels[i]) >> 5;
            if ((key >> 3) == c) {
                int lb = key & 7;
                int pos = atomicAdd(&s_cnt[lb], 1);
                if (pos < CAP2) s_list[lb][pos] = i;
            }
        }
        __syncthreads();

        int C = min(s_cnt[wid], CAP2);
        const float* Wn = W + (size_t)(33 + 8 * c + wid) * WNODE;
        int t = 0;
        while (C - t >= 5) {
            int G = min(8, C - t);
            int bs[8], step[8];
            #pragma unroll
            for (int s = 0; s < 8; s++) {
                int bb = s_list[wid][t + ((s < G) ? s : (G - 1))];
                bs[s] = bb;
                step[s] = __ldg(&labels[bb]) & 31;
            }
            unsigned msk = (G >= 8) ? 0xffu : ((1u << G) - 1u);
            process_run_reg<8>(x, Wn, bs, msk, step, lane, xsm, g_p + 2 * BTOT);
            t += G;
        }
        if (t < C) {
            int G = C - t;
            int bs[4], step[4];
            #pragma unroll
            for (int s = 0; s < 4; s++) {
                int bb = s_list[wid][t + ((s < G) ? s : (G - 1))];
                bs[s] = bb;
                step[s] = __ldg(&labels[bb]) & 31;
            }
            process_run_reg<4>(x, Wn, bs, (1u << G) - 1u, step, lane, xsm,
                               g_p + 2 * BTOT);
        }
    } else if (c < 192) {
        // ------------- level 0: node-0 W in smem, natural order ---------------
        #pragma unroll 4
        for (int idx = tid; idx < WPAIRS; idx += 256) {
            int p = idx >> 5, col = idx & 31;
            float a  = __ldg(W + (2 * p)     * BR + col);
            float bb = __ldg(W + (2 * p + 1) * BR + col);
            wps[idx] = packf2(a, bb);
        }
        __syncthreads();

        int s0 = (c - 128) * 64 + wid * 8;
        int bs[8], step[8];
        unsigned msk = 0;
        #pragma unroll
        for (int s = 0; s < 8; s++) {
            int bb = min(s0 + s, B - 1);
            bs[s] = bb;
            step[s] = (__ldg(&labels[bb]) >> 10) & 31;
            if (s0 + s < B) msk |= 1u << s;
        }
        process_run_smem(x, wps, bs, msk, step, lane, xsm, g_p);
    } else {
        // ------------- level 1: CTA per (node, parity), W in smem -------------
        int k = (c - 192) >> 1;
        int p = (c - 192) & 1;
        const float* Wn = W + (size_t)(1 + k) * WNODE;

        if (tid == 0) s_l1cnt = 0;
        __syncthreads();
        // W fill and filter interleave naturally (independent smem targets)
        #pragma unroll 4
        for (int idx = tid; idx < WPAIRS; idx += 256) {
            int pp = idx >> 5, col = idx & 31;
            float a  = __ldg(Wn + (2 * pp)     * BR + col);
            float bb = __ldg(Wn + (2 * pp + 1) * BR + col);
            wps[idx] = packf2(a, bb);
        }
        for (int i = tid; i < B; i += 256) {
            int lab = __ldg(&labels[i]);
            if ((lab >> 10) == k && (i & 1) == p) {
                int pos = atomicAdd(&s_l1cnt, 1);
                if (pos < CAP1) s_l1list[pos] = i;
            }
        }
        __syncthreads();

        int C = min(s_l1cnt, CAP1);
        int ntiles = (C + 7) >> 3;
        #pragma unroll 1
        for (int t = wid; t < ntiles; t += 8) {
            int t0 = t * 8;
            int G = min(8, C - t0);
            int bs[8], step[8];
            #pragma unroll
            for (int s = 0; s < 8; s++) {
                int bb = s_l1list[t0 + ((s < G) ? s : (G - 1))];
                bs[s] = bb;
                step[s] = (__ldg(&labels[bb]) >> 5) & 31;
            }
            unsigned msk = (G >= 8) ? 0xffu : ((1u << G) - 1u);
            process_run_smem(x, wps, bs, msk, step, lane, xsm, g_p + BTOT);
        }
    }

    // ---------------- completion: last CTA computes the product --------------
    __syncthreads();
    __threadfence();
    if (tid == 0) {
        int old = atomicAdd(&g_done, 1);
        s_last = (old == NCTA - 1) ? 1 : 0;
    }
    __syncthreads();
    if (s_last) {
        __threadfence();
        for (int i = tid; i < B; i += 256)
            out[i] = g_p[i] * g_p[BTOT + i] * g_p[2 * BTOT + i];
        if (tid == 0) g_done = 0;   // reset for next graph replay
    }
}

extern "C" void kernel_launch(void* const* d_in, const int* in_sizes, int n_in,
                              void* d_out, int out_size)
{
    const float* x      = (const float*)d_in[0];
    const int*   labels = (const int*)d_in[1];
    const float* W      = (const float*)d_in[2];
    float* out = (float*)d_out;

    int B = in_sizes[1];  // 4096

    cudaFuncSetAttribute(k_all, cudaFuncAttributeMaxDynamicSharedMemorySize,
                         DSMEM_BYTES);
    k_all<<<NCTA, 256, DSMEM_BYTES>>>(x, labels, W, out, B);
}

// round 16
// speedup vs baseline: 1.0942x; 1.0942x over previous
#include <cuda_runtime.h>
#include <cuda_bf16.h>
#include <cstdint>

// NLTKHierarchicalSoftmax: B=4096, NHID=512, BR=32, DEPTH=3
// Round 16 (final): champion configuration = Round 4 verbatim
// (sort -> work -> final; register double-buffered W; warp-private 8-sample
// runs; L0 natural / L1 sorted-tiles / L2 bucket-per-warp) with the
// isolated-better batched-load counting sort.

#define FULL 0xffffffffu
#define NHID 512
#define BR 32
#define NB2 1024
#define BTOT 4096
#define WNODE (NHID*BR)
#define NL0 512
#define NL1 512
#define WARPS_PER_CTA 8
#define NCTA 256

__device__ int g_off[NB2 + 1];
__device__ int g_sorted[BTOT];
__device__ float g_p[3 * BTOT];

typedef unsigned long long u64t;

__device__ __forceinline__ u64t ffma2(u64t a, u64t b, u64t c)
{
    u64t d;
    asm("fma.rn.f32x2 %0, %1, %2, %3;" : "=l"(d) : "l"(a), "l"(b), "l"(c));
    return d;
}
__device__ __forceinline__ u64t packf2(float lo, float hi)
{
    u64t d;
    asm("mov.b64 %0, {%1, %2};" : "=l"(d) : "f"(lo), "f"(hi));
    return d;
}
__device__ __forceinline__ float2 unpackf2(u64t v)
{
    float2 r;
    asm("mov.b64 {%0, %1}, %2;" : "=f"(r.x), "=f"(r.y) : "l"(v));
    return r;
}

// ---------------- counting sort (single CTA, 1024 thr, batched loads) ---------
__global__ void __launch_bounds__(NB2) k_sort(const int* __restrict__ labels, int B)
{
    __shared__ int cnt[NB2];
    __shared__ int cur[NB2];
    __shared__ int wsum[32];
    int t = threadIdx.x;
    int lane = t & 31;
    int warp = t >> 5;

    cnt[t] = 0;
    __syncthreads();

    int l0 = (t        < B) ? __ldg(&labels[t])        : -1;
    int l1 = (t + 1024 < B) ? __ldg(&labels[t + 1024]) : -1;
    int l2 = (t + 2048 < B) ? __ldg(&labels[t + 2048]) : -1;
    int l3 = (t + 3072 < B) ? __ldg(&labels[t + 3072]) : -1;
    if (l0 >= 0) atomicAdd(&cnt[l0 >> 5], 1);
    if (l1 >= 0) atomicAdd(&cnt[l1 >> 5], 1);
    if (l2 >= 0) atomicAdd(&cnt[l2 >> 5], 1);
    if (l3 >= 0) atomicAdd(&cnt[l3 >> 5], 1);
    __syncthreads();

    int v = cnt[t];
    int inc = v;
    #pragma unroll
    for (int o = 1; o < 32; o <<= 1) {
        int u = __shfl_up_sync(FULL, inc, o);
        if (lane >= o) inc += u;
    }
    if (lane == 31) wsum[warp] = inc;
    __syncthreads();
    if (t < 32) {
        int wv = wsum[t];
        int wi = wv;
        #pragma unroll
        for (int o = 1; o < 32; o <<= 1) {
            int u = __shfl_up_sync(FULL, wi, o);
            if (t >= o) wi += u;
        }
        wsum[t] = wi - wv;
    }
    __syncthreads();

    int excl = wsum[warp] + inc - v;
    g_off[t] = excl;
    cur[t] = excl;
    if (t == NB2 - 1) g_off[NB2] = excl + v;
    __syncthreads();

    if (l0 >= 0) g_sorted[atomicAdd(&cur[l0 >> 5], 1)] = t;
    if (l1 >= 0) g_sorted[atomicAdd(&cur[l1 >> 5], 1)] = t + 1024;
    if (l2 >= 0) g_sorted[atomicAdd(&cur[l2 >> 5], 1)] = t + 2048;
    if (l3 >= 0) g_sorted[atomicAdd(&cur[l3 >> 5], 1)] = t + 3072;
}

// ---------------- pipelined run processor (Round 4, verbatim) -----------------
template<int TS>
__device__ __forceinline__ void process_run(
    const float* __restrict__ x, const float* __restrict__ Wn,
    const int* bs, unsigned msk, const int* step,
    int lane, float (*xsm)[128], float* __restrict__ pout)
{
    u64t acc2[TS];
    #pragma unroll
    for (int s = 0; s < TS; s++) acc2[s] = 0ull;

    float wr[2][16];
    #pragma unroll
    for (int k = 0; k < 16; k++)
        wr[0][k] = __ldg(Wn + k * BR + lane);

    #pragma unroll 1
    for (int sc = 0; sc < 4; sc++) {            // 4 superchunks of 128 h
        __syncwarp();
        #pragma unroll
        for (int s = 0; s < TS; s++) {
            float4 xv = *(const float4*)(x + (size_t)bs[s] * NHID
                                         + sc * 128 + lane * 4);
            *(float4*)&xsm[s][lane * 4] = xv;
        }
        __syncwarp();

        #pragma unroll
        for (int sub = 0; sub < 8; sub++) {     // 8 subchunks of 16 h
            const int curb = sub & 1;
            const int subg = sc * 8 + sub;
            if (subg + 1 < 32) {                // prefetch next subchunk W
                int h0 = (subg + 1) * 16;
                #pragma unroll
                for (int k = 0; k < 16; k++)
                    wr[curb ^ 1][k] = __ldg(Wn + (h0 + k) * BR + lane);
            }
            u64t wp[8];
            #pragma unroll
            for (int k = 0; k < 8; k++)
                wp[k] = packf2(wr[curb][2 * k], wr[curb][2 * k + 1]);

            #pragma unroll
            for (int q = 0; q < 4; q++) {
                #pragma unroll
                for (int s = 0; s < TS; s++) {  // independent acc chains
                    ulonglong2 xq =
                        *(const ulonglong2*)&xsm[s][sub * 16 + q * 4];
                    acc2[s] = ffma2(xq.x, wp[2 * q], acc2[s]);
                    acc2[s] = ffma2(xq.y, wp[2 * q + 1], acc2[s]);
                }
            }
        }
    }

    // per-sample warp softmax over 32 columns (lane = column)
    #pragma unroll
    for (int s = 0; s < TS; s++) {
        if (msk & (1u << s)) {
            float2 h = unpackf2(acc2[s]);
            float acc = h.x + h.y;
            float m = acc;
            #pragma unroll
            for (int o = 16; o > 0; o >>= 1)
                m = fmaxf(m, __shfl_xor_sync(FULL, m, o));
            float e = __expf(acc - m);
            float sum = e;
            #pragma unroll
            for (int o = 16; o > 0; o >>= 1)
                sum += __shfl_xor_sync(FULL, sum, o);
            float est = __shfl_sync(FULL, e, step[s]);
            if (lane == 0) pout[bs[s]] = est / sum;
        }
    }
    __syncwarp();
}

// ---------------- work kernel (Round 4, verbatim) -----------------------------
__global__ void __launch_bounds__(32 * WARPS_PER_CTA, 2) k_work(
    const float* __restrict__ x, const int* __restrict__ labels,
    const float* __restrict__ W, int B)
{
    __shared__ __align__(16) float xs_tile[WARPS_PER_CTA][8][128];

    const int lane = threadIdx.x & 31;
    const int wid = threadIdx.x >> 5;
    int gw = blockIdx.x * WARPS_PER_CTA + wid;
    float (*xsm)[128] = xs_tile[wid];

    if (gw < NL0) {
        // level 0: node 0, natural order (no sort dependency)
        int s0 = gw * 8;
        int bs[8], step[8];
        unsigned msk = 0;
        #pragma unroll
        for (int s = 0; s < 8; s++) {
            int b = min(s0 + s, B - 1);
            bs[s] = b;
            step[s] = (__ldg(&labels[b]) >> 10) & 31;
            if (s0 + s < B) msk |= 1u << s;
        }
        process_run<8>(x, W, bs, msk, step, lane, xsm, g_p);
    } else if (gw < NL0 + NL1) {
        // level 1: tiles of 8 consecutive sorted samples; node = 1 + (lab>>10)
        int s0 = (gw - NL0) * 8;
        int bs[8], step[8], node[8];
        #pragma unroll
        for (int s = 0; s < 8; s++) {
            int idx = min(s0 + s, B - 1);
            int b = __ldg(&g_sorted[idx]);
            bs[s] = b;
            int lab = __ldg(&labels[b]);
            node[s] = 1 + (lab >> 10);
            step[s] = (lab >> 5) & 31;
        }
        unsigned valid = (s0 + 8 <= B) ? 0xffu : ((1u << (B - s0)) - 1u);
        unsigned rem = valid;
        while (rem) {
            int src = __ffs(rem) - 1;
            int n = node[src];
            unsigned msk = 0;
            #pragma unroll
            for (int s = 0; s < 8; s++)
                if (node[s] == n) msk |= 1u << s;
            msk &= valid;
            process_run<8>(x, W + (size_t)n * WNODE, bs, msk, step, lane, xsm,
                           g_p + BTOT);
            rem &= ~msk;
        }
    } else if (gw < NL0 + NL1 + NB2) {
        // level 2: one warp per bucket (node = 33 + bucket)
        int w = gw - NL0 - NL1;
        int beg = __ldg(&g_off[w]);
        int end = __ldg(&g_off[w + 1]);
        const float* Wn = W + (size_t)(33 + w) * WNODE;

        int t = beg;
        while (end - t >= 5) {
            int G = min(8, end - t);
            int bs[8], step[8];
            #pragma unroll
            for (int s = 0; s < 8; s++) {
                int idx = t + ((s < G) ? s : (G - 1));
                int b = __ldg(&g_sorted[idx]);
                bs[s] = b;
                step[s] = __ldg(&labels[b]) & 31;
            }
            unsigned msk = (G >= 8) ? 0xffu : ((1u << G) - 1u);
            process_run<8>(x, Wn, bs, msk, step, lane, xsm, g_p + 2 * BTOT);
            t += G;
        }
        if (t < end) {
            int G = end - t;
            int bs[4], step[4];
            #pragma unroll
            for (int s = 0; s < 4; s++) {
                int idx = t + ((s < G) ? s : (G - 1));
                int b = __ldg(&g_sorted[idx]);
                bs[s] = b;
                step[s] = __ldg(&labels[b]) & 31;
            }
            process_run<4>(x, Wn, bs, (1u << G) - 1u, step, lane, xsm,
                           g_p + 2 * BTOT);
        }
    }
}

__global__ void k_final(float* __restrict__ out, int B)
{
    int i = blockIdx.x * blockDim.x + threadIdx.x;
    if (i < B) out[i] = g_p[i] * g_p[BTOT + i] * g_p[2 * BTOT + i];
}

extern "C" void kernel_launch(void* const* d_in, const int* in_sizes, int n_in,
                              void* d_out, int out_size)
{
    const float* x      = (const float*)d_in[0];
    const int*   labels = (const int*)d_in[1];
    const float* W      = (const float*)d_in[2];
    float* out = (float*)d_out;

    int B = in_sizes[1];  // 4096

    k_sort<<<1, NB2>>>(labels, B);
    k_work<<<NCTA, 256>>>(x, labels, W, B);
    k_final<<<(B + 255) / 256, 256>>>(out, B);
}